// round 8
// baseline (speedup 1.0000x reference)
#include <cuda_runtime.h>
#include <cstdint>

// Spike-latency encoder:
//   trace:  [B=1024, F=128] f32,  center: [C=8] f32
//   out:    [T=100, B=1024, N=F*C=1024] f32 one-hot along T per (b,n)
//
// out[t,b,f*8+c] = (bin(b,f,c) == t) ? 1.0f : 0.0f
//   bin = trunc( sel(2.5*|trace[b,f]-center[c]|) / 0.1 + 1 )
//   sel(x) = (x > 10.0f) ? 10.1f : x     (bin -> 102, never matches)
//
// 419 MB write stream at the ~6.2 TB/s write wall (R3-R7 sweep). R8: 256-bit
// stores (st.global.cs.v8.f32, sm_100+). One thread = one feature = 8
// consecutive n = one 32B store per t-slab. Block = 2 b-rows x 128 features.

#define BB 1024
#define FF 128
#define CC 8
#define NN 1024
#define TT 100
#define NCH 20          // t-chunks
#define TCH 5           // t-slabs per chunk

__device__ __forceinline__ void stcs_v8(float* p,
                                        float a, float b, float c, float d,
                                        float e, float f, float g, float h) {
    asm volatile("st.global.cs.v8.f32 [%0], {%1,%2,%3,%4,%5,%6,%7,%8};"
                 :: "l"(p), "f"(a), "f"(b), "f"(c), "f"(d),
                    "f"(e), "f"(f), "f"(g), "f"(h)
                 : "memory");
}

__global__ void __launch_bounds__(256, 8)
spike_latency_kernel(const float* __restrict__ trace,
                     const float* __restrict__ center,
                     float* __restrict__ out) {
    const int br  = blockIdx.x & 511;        // b-row pair, 0..511 (fast)
    const int tc  = blockIdx.x >> 9;         // 0..19 t-chunk
    const int tid = threadIdx.x;             // 0..255
    const int b   = (br << 1) + (tid >> 7);  // 2 b-rows per block
    const int f   = tid & 127;               // one feature per thread
    const int n0  = f << 3;                  // 8 consecutive n (32B aligned)

    const float tv = __ldg(&trace[b * FF + f]);

    int bins[8];
#pragma unroll
    for (int c = 0; c < CC; c++) {
        float tm = 2.5f * fabsf(tv - __ldg(&center[c]));   // SCALING*|diff|
        if (tm > 10.0f) tm = 10.1f;                        // cutoff -> T+DT
        // trunc(times/DT + 1), IEEE f32 divide (bit-match XLA div.rn:
        // one flipped bin alone would exceed the 1e-3 rel_err budget)
        bins[c] = (int)(__fdiv_rn(tm, 0.1f) + 1.0f);
    }

    const size_t strideT = (size_t)BB * NN;            // floats per t-slab
    float* outp = out + (size_t)b * NN + n0
                + (size_t)(tc * TCH) * strideT;

    const int tbase = tc * TCH;
#pragma unroll
    for (int i = 0; i < TCH; i++) {
        const int t = tbase + i;
        stcs_v8(outp + (size_t)i * strideT,
                (bins[0] == t) ? 1.0f : 0.0f,
                (bins[1] == t) ? 1.0f : 0.0f,
                (bins[2] == t) ? 1.0f : 0.0f,
                (bins[3] == t) ? 1.0f : 0.0f,
                (bins[4] == t) ? 1.0f : 0.0f,
                (bins[5] == t) ? 1.0f : 0.0f,
                (bins[6] == t) ? 1.0f : 0.0f,
                (bins[7] == t) ? 1.0f : 0.0f);
    }
}

extern "C" void kernel_launch(void* const* d_in, const int* in_sizes, int n_in,
                              void* d_out, int out_size) {
    // Identify inputs by element count — robust to metadata ordering:
    //   trace: 131072 floats, center: 8 floats, dummies: 1 each
    const float* trace  = nullptr;
    const float* center = nullptr;
    for (int i = 0; i < n_in; i++) {
        if (in_sizes[i] == BB * FF)     trace  = (const float*)d_in[i];
        else if (in_sizes[i] == CC)     center = (const float*)d_in[i];
    }
    if (!trace)  trace  = (const float*)d_in[0];
    if (!center) center = (const float*)d_in[1];

    float* out = (float*)d_out;  // [100, 1024, 1024] f32 one-hot

    spike_latency_kernel<<<(BB / 2) * NCH, 256>>>(trace, center, out);
}

// round 9
// speedup vs baseline: 1.0234x; 1.0234x over previous
#include <cuda_runtime.h>
#include <cstdint>

// Spike-latency encoder:
//   trace:  [B=1024, F=128] f32,  center: [C=8] f32
//   out:    [T=100, B=1024, N=F*C=1024] f32 one-hot along T per (b,n)
//
// out[t,b,f*8+c] = (bin(b,f,c) == t) ? 1.0f : 0.0f
//   bin = trunc( sel(2.5*|trace[b,f]-center[c]|) / 0.1 + 1 )
//   sel(x) = (x > 10.0f) ? 10.1f : x     (bin -> 102, never matches)
//
// 419 MB pure write stream at the ~6.2 TB/s DRAM write wall (R3-R8 sweep:
// concurrency monotone helps, v8 stores hurt via grid halving). R9 = R7
// winner with a 25-way t-split (TCH=4, grid 25600) for max store-queue
// concurrency and smallest last-wave tail.

#define BB 1024
#define FF 128
#define CC 8
#define NN 1024
#define TT 100
#define NCH 25          // t-chunks
#define TCH 4           // t-slabs per chunk

__global__ void __launch_bounds__(256, 8)
spike_latency_kernel(const float* __restrict__ trace,
                     const float* __restrict__ center,
                     float* __restrict__ out) {
    const int b   = blockIdx.x & (BB - 1);   // 0..1023 (fast-varying)
    const int tc  = blockIdx.x >> 10;        // 0..24   t-chunk
    const int tid = threadIdx.x;             // 0..255
    const int n0  = tid << 2;                // 4 consecutive n per thread
    const int f   = n0 >> 3;                 // all 4 n share one feature
    const int c0  = n0 & 7;                  // 0 or 4

    const float tv = __ldg(&trace[b * FF + f]);

    int bins[4];
#pragma unroll
    for (int j = 0; j < 4; j++) {
        float ct = __ldg(&center[c0 + j]);
        float tm = 2.5f * fabsf(tv - ct);          // SCALING * |diff|  (f32)
        if (tm > 10.0f) tm = 10.1f;                // cutoff -> TIME_LENGTH + DT
        // trunc(times/DT + 1), IEEE f32 divide (bit-match XLA div.rn:
        // one flipped bin alone would exceed the 1e-3 rel_err budget)
        bins[j] = (int)(__fdiv_rn(tm, 0.1f) + 1.0f);
    }

    const size_t stride4 = (size_t)BB * NN / 4;    // 262144 float4 per t-slab
    float4* outp = reinterpret_cast<float4*>(out + (size_t)b * NN + n0)
                 + (size_t)(tc * TCH) * stride4;

    const int tbase = tc * TCH;
#pragma unroll
    for (int i = 0; i < TCH; i++) {
        const int t = tbase + i;
        float4 v;
        v.x = (bins[0] == t) ? 1.0f : 0.0f;
        v.y = (bins[1] == t) ? 1.0f : 0.0f;
        v.z = (bins[2] == t) ? 1.0f : 0.0f;
        v.w = (bins[3] == t) ? 1.0f : 0.0f;
        __stcs(outp + (size_t)i * stride4, v);     // streaming store
    }
}

extern "C" void kernel_launch(void* const* d_in, const int* in_sizes, int n_in,
                              void* d_out, int out_size) {
    // Identify inputs by element count — robust to metadata ordering:
    //   trace: 131072 floats, center: 8 floats, dummies: 1 each
    const float* trace  = nullptr;
    const float* center = nullptr;
    for (int i = 0; i < n_in; i++) {
        if (in_sizes[i] == BB * FF)     trace  = (const float*)d_in[i];
        else if (in_sizes[i] == CC)     center = (const float*)d_in[i];
    }
    if (!trace)  trace  = (const float*)d_in[0];
    if (!center) center = (const float*)d_in[1];

    float* out = (float*)d_out;  // [100, 1024, 1024] f32 one-hot

    spike_latency_kernel<<<BB * NCH, 256>>>(trace, center, out);
}